// round 6
// baseline (speedup 1.0000x reference)
#include <cuda_runtime.h>
#include <stdint.h>

// HypervectorEngine: 512x8192 f32 -> 512x4096 f32 sparse sign output.
// seed = i ^ round(sig*1000) in [0,1024) -> only 1024 distinct hypervectors.
// K1: bit-packed sign table (4.2M threefry, pipe-balanced IMAD/alu; at alu roofline).
// K2: per-row combine, 4-way sample split (25 samples -> 5 bit-planes) for
//     ~86% occupancy, redundant 4-way merge, fused top-k select.
// RNG: JAX partitionable threefry, word_j = o0 ^ o1 of threefry(key,(0,j)). (verified R2)

#define NSAMP   100
#define QSAMP   25
#define DIMV    4096
#define KSEL    2048
#define LSIG    8192
#define NSEEDS  1024
#define WPR     (DIMV / 32)        // 128 packed words per hypervector

__device__ uint32_t g_hv[NSEEDS * WPR];

// Force add onto the FMA pipe: d = a*one + b ('one' runtime-opaque).
__device__ __forceinline__ uint32_t addi(uint32_t a, uint32_t b, uint32_t one) {
    uint32_t d;
    asm("mad.lo.u32 %0, %1, %2, %3;" : "=r"(d) : "r"(a), "r"(one), "r"(b));
    return d;
}

// JAX threefry2x32, key (0,42), counter (0,c1) -> derived key (fold_in). Cold path.
__device__ __forceinline__ void threefry_key(uint32_t c1, uint32_t& o0, uint32_t& o1)
{
    const uint32_t k0 = 0u, k1 = 42u, k2 = 0u ^ 42u ^ 0x1BD11BDAu;
    uint32_t x0 = k0, x1 = c1 + k1;
    #define R(r) { x0 += x1; x1 = __funnelshift_l(x1, x1, r); x1 ^= x0; }
    R(13) R(15) R(26) R(6)  x0 += k1; x1 += k2 + 1u;
    R(17) R(29) R(16) R(24) x0 += k2; x1 += k0 + 2u;
    R(13) R(15) R(26) R(6)  x0 += k0; x1 += k1 + 3u;
    R(17) R(29) R(16) R(24) x0 += k1; x1 += k2 + 4u;
    R(13) R(15) R(26) R(6)
    o0 = x0 + k2; o1 = x1 + k0 + 5u;
    #undef R
}

// ---------------- Kernel 1: build hypervector sign table ----------------
__global__ void __launch_bounds__(256)
hv_table_kernel(uint32_t one)
{
    const int seed = blockIdx.x;
    const int t    = threadIdx.x;
    const int lane = t & 31;
    const int wrp  = t >> 5;

    __shared__ uint32_t sk0, sk1;
    if (t == 0) {
        uint32_t o0, o1;
        threefry_key((uint32_t)seed, o0, o1);
        sk0 = o0; sk1 = o1;
    }
    __syncthreads();
    const uint32_t k0 = sk0, k1 = sk1, k2 = k0 ^ k1 ^ 0x1BD11BDAu;
    const uint32_t k2p1 = k2 + 1u, k0p2 = k0 + 2u, k1p3 = k1 + 3u;
    const uint32_t k2p4 = k2 + 4u, k0p5 = k0 + 5u;
    const uint32_t k1t  = k1 + (uint32_t)t;

    uint32_t* dst = g_hv + (size_t)seed * WPR;
#pragma unroll
    for (int p = 0; p < DIMV / 256; p++) {       // 16 hashes per thread
        uint32_t x0 = k0;
        uint32_t x1 = addi(k1t, (uint32_t)(p * 256), one);
        #define RB(r) { x0 = addi(x0, x1, one); x1 = __funnelshift_l(x1, x1, r); x1 ^= x0; }
        RB(13) RB(15) RB(26) RB(6)
        x0 = addi(x0, k1, one); x1 = addi(x1, k2p1, one);
        RB(17) RB(29) RB(16) RB(24)
        x0 = addi(x0, k2, one); x1 = addi(x1, k0p2, one);
        RB(13) RB(15) RB(26) RB(6)
        x0 = addi(x0, k0, one); x1 = addi(x1, k1p3, one);
        RB(17) RB(29) RB(16) RB(24)
        x0 = addi(x0, k1, one); x1 = addi(x1, k2p4, one);
        RB(13) RB(15) RB(26) RB(6)
        #undef RB
        const uint32_t o0 = addi(x0, k2, one);
        const uint32_t o1 = addi(x1, k0p5, one);
        const uint32_t word = __ballot_sync(0xFFFFFFFFu, (int)((o0 ^ o1) >> 31));
        if (lane == 0) dst[p * 8 + wrp] = word;
    }
}

// ---------------- Kernel 2: combine + top-k select (fused) ----------------
#define C_THREADS 512
#define C_BPT     8                // output elems per thread in epilogue

__global__ void __launch_bounds__(C_THREADS)
hv_combine_kernel(const float* __restrict__ sig, float* __restrict__ out)
{
    const int b = blockIdx.x;
    const int t = threadIdx.x;

    __shared__ int      sseed[NSAMP];
    __shared__ uint32_t spl[4][5][WPR];   // [quarter][plane][word], 10 KB
    __shared__ int      shist[51];
    __shared__ int      sscan[C_THREADS];
    __shared__ int      sT, sQuota;

    if (t < NSAMP) {
        const int i   = t;
        const int idx = (i * (LSIG - 1)) / (NSAMP - 1);   // trunc of f32 linspace
        const float s = sig[(size_t)b * LSIG + idx];
        const int val = __float2int_rn(s * 1000.0f);      // jnp.round RNE
        sseed[i] = i ^ val;                                // in [0,1024)
    }
    if (t < 51) shist[t] = 0;
    __syncthreads();

    // ---- accumulate: thread t -> word w, sample-quarter qt (25 samples, 5 planes) ----
    {
        const int w  = t & (WPR - 1);
        const int qt = t >> 7;                 // 0..3
        const int ibase = qt * QSAMP;

        uint32_t p0=0,p1=0,p2=0,p3=0,p4=0;
#pragma unroll
        for (int i = 0; i < QSAMP; i++) {
            uint32_t ca = g_hv[(size_t)sseed[ibase + i] * WPR + w];
            uint32_t s;
            s = p0 ^ ca; ca &= p0; p0 = s;
            s = p1 ^ ca; ca &= p1; p1 = s;
            s = p2 ^ ca; ca &= p2; p2 = s;
            s = p3 ^ ca; ca &= p3; p3 = s;
            p4 ^= ca;
        }
        spl[qt][0][w] = p0; spl[qt][1][w] = p1; spl[qt][2][w] = p2;
        spl[qt][3][w] = p3; spl[qt][4][w] = p4;
    }
    __syncthreads();

    // ---- merge 4 quarters for word w3 = t>>2; extract bits [(t&3)*8, +8) ----
    const int w3 = t >> 2;
    const int lbase = (t & 3) * C_BPT;

    uint32_t a0 = spl[0][0][w3], a1 = spl[0][1][w3], a2 = spl[0][2][w3],
             a3 = spl[0][3][w3], a4 = spl[0][4][w3];
    uint32_t b0 = spl[1][0][w3], b1 = spl[1][1][w3], b2 = spl[1][2][w3],
             b3 = spl[1][3][w3], b4 = spl[1][4][w3];
    uint32_t c0 = spl[2][0][w3], c1 = spl[2][1][w3], c2 = spl[2][2][w3],
             c3 = spl[2][3][w3], c4 = spl[2][4][w3];
    uint32_t d0 = spl[3][0][w3], d1 = spl[3][1][w3], d2 = spl[3][2][w3],
             d3 = spl[3][3][w3], d4 = spl[3][4][w3];

    // add5: (a)+(b) -> m (6 planes); (c)+(d) -> n (6 planes)
    uint32_t m0,m1,m2,m3,m4,m5, n0,n1,n2,n3,n4,n5, cy;
    m0 = a0 ^ b0;        cy = a0 & b0;
    m1 = a1 ^ b1 ^ cy;   cy = (a1 & b1) | (cy & (a1 ^ b1));
    m2 = a2 ^ b2 ^ cy;   cy = (a2 & b2) | (cy & (a2 ^ b2));
    m3 = a3 ^ b3 ^ cy;   cy = (a3 & b3) | (cy & (a3 ^ b3));
    m4 = a4 ^ b4 ^ cy;   cy = (a4 & b4) | (cy & (a4 ^ b4));
    m5 = cy;
    n0 = c0 ^ d0;        cy = c0 & d0;
    n1 = c1 ^ d1 ^ cy;   cy = (c1 & d1) | (cy & (c1 ^ d1));
    n2 = c2 ^ d2 ^ cy;   cy = (c2 & d2) | (cy & (c2 ^ d2));
    n3 = c3 ^ d3 ^ cy;   cy = (c3 & d3) | (cy & (c3 ^ d3));
    n4 = c4 ^ d4 ^ cy;   cy = (c4 & d4) | (cy & (c4 ^ d4));
    n5 = cy;

    // add6: m + n -> r (7 planes)
    uint32_t r0,r1,r2,r3,r4,r5,r6;
    r0 = m0 ^ n0;        cy = m0 & n0;
    r1 = m1 ^ n1 ^ cy;   cy = (m1 & n1) | (cy & (m1 ^ n1));
    r2 = m2 ^ n2 ^ cy;   cy = (m2 & n2) | (cy & (m2 ^ n2));
    r3 = m3 ^ n3 ^ cy;   cy = (m3 & n3) | (cy & (m3 ^ n3));
    r4 = m4 ^ n4 ^ cy;   cy = (m4 & n4) | (cy & (m4 ^ n4));
    r5 = m5 ^ n5 ^ cy;   cy = (m5 & n5) | (cy & (m5 ^ n5));
    r6 = cy;

    int cval[C_BPT];
#pragma unroll
    for (int q = 0; q < C_BPT; q++) {
        const int l = lbase + q;
        int n =  (int)((r0 >> l) & 1u)
              + ((int)((r1 >> l) & 1u) << 1)
              + ((int)((r2 >> l) & 1u) << 2)
              + ((int)((r3 >> l) & 1u) << 3)
              + ((int)((r4 >> l) & 1u) << 4)
              + ((int)((r5 >> l) & 1u) << 5)
              + ((int)((r6 >> l) & 1u) << 6);
        cval[q] = NSAMP - 2 * n;     // combined[j], j = t*8 + q
    }

    // ---- histogram of |c|/2 (bins 0..50) ----
#pragma unroll
    for (int q = 0; q < C_BPT; q++) {
        int a = cval[q] < 0 ? -cval[q] : cval[q];
        atomicAdd(&shist[a >> 1], 1);
    }
    __syncthreads();

    // ---- threshold T and tie quota ----
    if (t == 0) {
        int cum = 0, T = 0, quota = 0;
        for (int v = 50; v >= 0; v--) {
            int h = shist[v];
            if (cum + h >= KSEL) { T = v * 2; quota = KSEL - cum; break; }
            cum += h;
        }
        sT = T; sQuota = quota;
    }
    __syncthreads();
    const int T = sT, quota = sQuota;

    // ---- ordered block scan of (|c|==T): stable index tie-break ----
    int eq = 0;
#pragma unroll
    for (int q = 0; q < C_BPT; q++) {
        int a = cval[q] < 0 ? -cval[q] : cval[q];
        eq += (a == T);
    }
    sscan[t] = eq;
    __syncthreads();
    for (int off = 1; off < C_THREADS; off <<= 1) {
        int v = sscan[t];
        int add = (t >= off) ? sscan[t - off] : 0;
        __syncthreads();
        sscan[t] = v + add;
        __syncthreads();
    }
    int rank = sscan[t] - eq;

    // ---- write output (j = t*8 + q) ----
    float* orow = out + (size_t)b * DIMV + t * C_BPT;
#pragma unroll
    for (int q = 0; q < C_BPT; q++) {
        const int cc = cval[q];
        const int a  = cc < 0 ? -cc : cc;
        float v = 0.0f;
        if (a > T) {
            v = (cc > 0) ? 1.0f : -1.0f;
        } else if (a == T) {
            if (rank < quota) v = (cc > 0) ? 1.0f : ((cc < 0) ? -1.0f : 0.0f);
            rank++;
        }
        orow[q] = v;
    }
}

extern "C" void kernel_launch(void* const* d_in, const int* in_sizes, int n_in,
                              void* d_out, int out_size)
{
    const float* sig = (const float*)d_in[0];
    float* out = (float*)d_out;
    const int B = in_sizes[0] / LSIG;   // 512
    hv_table_kernel<<<NSEEDS, 256>>>(1u);
    hv_combine_kernel<<<B, C_THREADS>>>(sig, out);
}

// round 7
// speedup vs baseline: 1.3229x; 1.3229x over previous
#include <cuda_runtime.h>
#include <stdint.h>

// HypervectorEngine: 512x8192 f32 -> 512x4096 f32 sparse sign output.
// seed = i ^ round(sig*1000) in [0,1024) -> 1024 distinct hypervectors.
// K1: bit-packed sign table (4.2M threefry, IMAD/alu pipe-balanced; at alu roofline).
// K2: combine, 2x50 sample split, CSA-tree bit-sliced accumulate (3.2x fewer LOP3),
//     byte-packed decode, shfl scans, warp-parallel threshold.
// RNG: JAX partitionable threefry, word_j = o0 ^ o1 of threefry(key,(0,j)). (verified R2)

#define NSAMP   100
#define HSAMP   50
#define DIMV    4096
#define KSEL    2048
#define LSIG    8192
#define NSEEDS  1024
#define WPR     (DIMV / 32)        // 128 packed words per hypervector

__device__ uint32_t g_hv[NSEEDS * WPR];

__device__ __forceinline__ uint32_t addi(uint32_t a, uint32_t b, uint32_t one) {
    uint32_t d;
    asm("mad.lo.u32 %0, %1, %2, %3;" : "=r"(d) : "r"(a), "r"(one), "r"(b));
    return d;
}

__device__ __forceinline__ uint32_t xor3(uint32_t a, uint32_t b, uint32_t c) {
    return a ^ b ^ c;                       // 1 LOP3
}
__device__ __forceinline__ uint32_t maj3(uint32_t a, uint32_t b, uint32_t c) {
    return (a & b) | (c & (a | b));         // 1 LOP3
}

// JAX threefry2x32, key (0,42), counter (0,c1) -> derived key (fold_in). Cold path.
__device__ __forceinline__ void threefry_key(uint32_t c1, uint32_t& o0, uint32_t& o1)
{
    const uint32_t k0 = 0u, k1 = 42u, k2 = 0u ^ 42u ^ 0x1BD11BDAu;
    uint32_t x0 = k0, x1 = c1 + k1;
    #define R(r) { x0 += x1; x1 = __funnelshift_l(x1, x1, r); x1 ^= x0; }
    R(13) R(15) R(26) R(6)  x0 += k1; x1 += k2 + 1u;
    R(17) R(29) R(16) R(24) x0 += k2; x1 += k0 + 2u;
    R(13) R(15) R(26) R(6)  x0 += k0; x1 += k1 + 3u;
    R(17) R(29) R(16) R(24) x0 += k1; x1 += k2 + 4u;
    R(13) R(15) R(26) R(6)
    o0 = x0 + k2; o1 = x1 + k0 + 5u;
    #undef R
}

// ---------------- Kernel 1: build hypervector sign table ----------------
__global__ void __launch_bounds__(256)
hv_table_kernel(uint32_t one)
{
    const int seed = blockIdx.x;
    const int t    = threadIdx.x;
    const int lane = t & 31;
    const int wrp  = t >> 5;

    __shared__ uint32_t sk0, sk1;
    if (t == 0) {
        uint32_t o0, o1;
        threefry_key((uint32_t)seed, o0, o1);
        sk0 = o0; sk1 = o1;
    }
    __syncthreads();
    const uint32_t k0 = sk0, k1 = sk1, k2 = k0 ^ k1 ^ 0x1BD11BDAu;
    const uint32_t k2p1 = k2 + 1u, k0p2 = k0 + 2u, k1p3 = k1 + 3u;
    const uint32_t k2p4 = k2 + 4u, k0p5 = k0 + 5u;
    const uint32_t k1t  = k1 + (uint32_t)t;

    uint32_t* dst = g_hv + (size_t)seed * WPR;
#pragma unroll
    for (int p = 0; p < DIMV / 256; p++) {
        uint32_t x0 = k0;
        uint32_t x1 = addi(k1t, (uint32_t)(p * 256), one);
        #define RB(r) { x0 = addi(x0, x1, one); x1 = __funnelshift_l(x1, x1, r); x1 ^= x0; }
        RB(13) RB(15) RB(26) RB(6)
        x0 = addi(x0, k1, one); x1 = addi(x1, k2p1, one);
        RB(17) RB(29) RB(16) RB(24)
        x0 = addi(x0, k2, one); x1 = addi(x1, k0p2, one);
        RB(13) RB(15) RB(26) RB(6)
        x0 = addi(x0, k0, one); x1 = addi(x1, k1p3, one);
        RB(17) RB(29) RB(16) RB(24)
        x0 = addi(x0, k1, one); x1 = addi(x1, k2p4, one);
        RB(13) RB(15) RB(26) RB(6)
        #undef RB
        const uint32_t o0 = addi(x0, k2, one);
        const uint32_t o1 = addi(x1, k0p5, one);
        const uint32_t word = __ballot_sync(0xFFFFFFFFu, (int)((o0 ^ o1) >> 31));
        if (lane == 0) dst[p * 8 + wrp] = word;
    }
}

// ---------------- Kernel 2: combine + top-k select (fused) ----------------
#define C_THREADS 256
#define C_BPT     16               // output elems per thread in select phase

__global__ void __launch_bounds__(C_THREADS)
hv_combine_kernel(const float* __restrict__ sig, float* __restrict__ out)
{
    const int b = blockIdx.x;
    const int t = threadIdx.x;
    const int lane = t & 31;
    const int wid  = t >> 5;

    __shared__ int      sseed[NSAMP];
    __shared__ uint32_t spl[2][6][WPR];     // [half][plane][word], 6 KB
    __shared__ uint32_t squad[WPR * 8];     // packed n-bytes, 4 KB
    __shared__ int      shist[51];
    __shared__ int      swsum[C_THREADS / 32];
    __shared__ int      sTb, sQuota;

    if (t < NSAMP) {
        const int i   = t;
        const int idx = (i * (LSIG - 1)) / (NSAMP - 1);   // trunc of f32 linspace
        const float s = sig[(size_t)b * LSIG + idx];
        const int val = __float2int_rn(s * 1000.0f);      // jnp.round RNE
        sseed[i] = i ^ val;                                // in [0,1024)
    }
    if (t < 51) shist[t] = 0;
    __syncthreads();

    const int w = t & (WPR - 1);
    const int h = t >> 7;                  // sample half 0/1

    // ---- accumulate 50 samples into 6 bit-planes via CSA groups of 5 ----
    {
        const uint32_t* tbl = g_hv;
        const int ibase = h * HSAMP;
        uint32_t p0=0,p1=0,p2=0,p3=0,p4=0,p5=0;
#pragma unroll
        for (int g = 0; g < HSAMP / 5; g++) {
            const int i0 = ibase + g * 5;
            uint32_t w0 = tbl[(size_t)sseed[i0    ] * WPR + w];
            uint32_t w1 = tbl[(size_t)sseed[i0 + 1] * WPR + w];
            uint32_t w2 = tbl[(size_t)sseed[i0 + 2] * WPR + w];
            uint32_t w3 = tbl[(size_t)sseed[i0 + 3] * WPR + w];
            uint32_t w4 = tbl[(size_t)sseed[i0 + 4] * WPR + w];
            // sum of 5 one-bit planes -> (g1, g2, g4)
            uint32_t s1 = xor3(w0, w1, w2);
            uint32_t c1 = maj3(w0, w1, w2);
            uint32_t g1 = xor3(s1, w3, w4);
            uint32_t c2 = maj3(s1, w3, w4);
            uint32_t g2 = c1 ^ c2;
            uint32_t g4 = c1 & c2;
            // add (g1,g2,g4) into accumulator planes p0..p5
            uint32_t cy;
            cy = p0 & g1;            p0 ^= g1;
            uint32_t n1 = xor3(p1, g2, cy); cy = maj3(p1, g2, cy); p1 = n1;
            uint32_t n2 = xor3(p2, g4, cy); cy = maj3(p2, g4, cy); p2 = n2;
            uint32_t n3 = p3 ^ cy;   cy &= p3;                     p3 = n3;
            uint32_t n4 = p4 ^ cy;   cy &= p4;                     p4 = n4;
            p5 ^= cy;
        }
        spl[h][0][w] = p0; spl[h][1][w] = p1; spl[h][2][w] = p2;
        spl[h][3][w] = p3; spl[h][4][w] = p4; spl[h][5][w] = p5;
    }
    __syncthreads();

    // ---- merge halves for word w; decode 4 quads per thread into n-bytes ----
    {
        uint32_t a0 = spl[0][0][w], a1 = spl[0][1][w], a2 = spl[0][2][w],
                 a3 = spl[0][3][w], a4 = spl[0][4][w], a5 = spl[0][5][w];
        uint32_t b0 = spl[1][0][w], b1 = spl[1][1][w], b2 = spl[1][2][w],
                 b3 = spl[1][3][w], b4 = spl[1][4][w], b5 = spl[1][5][w];
        uint32_t r0,r1,r2,r3,r4,r5,r6, cy;
        r0 = a0 ^ b0;          cy = a0 & b0;
        r1 = xor3(a1,b1,cy);   cy = maj3(a1,b1,cy);
        r2 = xor3(a2,b2,cy);   cy = maj3(a2,b2,cy);
        r3 = xor3(a3,b3,cy);   cy = maj3(a3,b3,cy);
        r4 = xor3(a4,b4,cy);   cy = maj3(a4,b4,cy);
        r5 = xor3(a5,b5,cy);   cy = maj3(a5,b5,cy);
        r6 = cy;

        const int lb = h * 4;              // quads l = lb..lb+3
#pragma unroll
        for (int q = 0; q < 4; q++) {
            const int l = lb + q;
            uint32_t acc;
            acc  =  (r0 >> l) & 0x01010101u;
            acc += ((r1 >> l) & 0x01010101u) << 1;
            acc += ((r2 >> l) & 0x01010101u) << 2;
            acc += ((r3 >> l) & 0x01010101u) << 3;
            acc += ((r4 >> l) & 0x01010101u) << 4;
            acc += ((r5 >> l) & 0x01010101u) << 5;
            acc += ((r6 >> l) & 0x01010101u) << 6;
            squad[w * 8 + l] = acc;        // byte k = n for element w*32 + l + 8k
        }
    }
    __syncthreads();

    // ---- select phase: thread t owns elements j = t*16 .. t*16+15 ----
    // j = w2*32 + hb*16 + q : word w2*8 + (q&7), byte 2*hb + (q>>3)
    const int w2 = t >> 1;
    const int hb = t & 1;

    int nv[C_BPT];
#pragma unroll
    for (int q = 0; q < C_BPT; q++) {
        const uint32_t word = squad[w2 * 8 + (q & 7)];
        nv[q] = (int)((word >> (8 * (2 * hb + (q >> 3)))) & 0xFFu);
    }

    // histogram over bins |n-50| in 0..50
#pragma unroll
    for (int q = 0; q < C_BPT; q++) {
        int d = nv[q] - 50;
        int bin = d < 0 ? -d : d;
        atomicAdd(&shist[bin], 1);
    }
    __syncthreads();

    // ---- threshold: warp-parallel suffix scan over 51 bins ----
    if (t < 32) {
        // segment 1: bins 50..19 (lane l -> bin 50-l)
        int h1 = shist[50 - t];
        int c1 = h1;
#pragma unroll
        for (int off = 1; off < 32; off <<= 1) {
            int y = __shfl_up_sync(0xFFFFFFFFu, c1, off);
            if (t >= off) c1 += y;
        }
        int total_hi = __shfl_sync(0xFFFFFFFFu, c1, 31);
        if (c1 >= KSEL && c1 - h1 < KSEL) { sTb = 50 - t; sQuota = KSEL - (c1 - h1); }
        // segment 2: bins 18..0 (lane l<19 -> bin 18-l)
        int h2 = (t < 19) ? shist[18 - t] : 0;
        int c2 = h2;
#pragma unroll
        for (int off = 1; off < 32; off <<= 1) {
            int y = __shfl_up_sync(0xFFFFFFFFu, c2, off);
            if (t >= off) c2 += y;
        }
        int cum2 = total_hi + c2;
        if (t < 19 && cum2 >= KSEL && cum2 - h2 < KSEL) { sTb = 18 - t; sQuota = KSEL - (cum2 - h2); }
    }
    __syncthreads();
    const int Tb = sTb, quota = sQuota;

    // ---- rank of ties (|n-50|==Tb) before this thread, via shfl scans ----
    int eq = 0;
#pragma unroll
    for (int q = 0; q < C_BPT; q++) {
        int d = nv[q] - 50;
        int bin = d < 0 ? -d : d;
        eq += (bin == Tb);
    }
    int inc = eq;
#pragma unroll
    for (int off = 1; off < 32; off <<= 1) {
        int y = __shfl_up_sync(0xFFFFFFFFu, inc, off);
        if (lane >= off) inc += y;
    }
    if (lane == 31) swsum[wid] = inc;
    __syncthreads();
    if (t < C_THREADS / 32) {
        int v = swsum[t];
        int s = v;
#pragma unroll
        for (int off = 1; off < C_THREADS / 32; off <<= 1) {
            int y = __shfl_up_sync(0xFFu, s, off);
            if (t >= off) s += y;
        }
        swsum[t] = s - v;      // exclusive warp offset
    }
    __syncthreads();
    int rank = swsum[wid] + (inc - eq);

    // ---- write output (j = t*16 + q), float4 vectorized ----
    float4* orow = reinterpret_cast<float4*>(out + (size_t)b * DIMV + t * C_BPT);
#pragma unroll
    for (int v4 = 0; v4 < C_BPT / 4; v4++) {
        float vv[4];
#pragma unroll
        for (int e = 0; e < 4; e++) {
            const int d = 50 - nv[v4 * 4 + e];      // cval/2
            const int a = d < 0 ? -d : d;
            float v = 0.0f;
            if (a > Tb) {
                v = (d > 0) ? 1.0f : -1.0f;
            } else if (a == Tb) {
                if (rank < quota) v = (d > 0) ? 1.0f : ((d < 0) ? -1.0f : 0.0f);
                rank++;
            }
            vv[e] = v;
        }
        orow[v4] = make_float4(vv[0], vv[1], vv[2], vv[3]);
    }
}

extern "C" void kernel_launch(void* const* d_in, const int* in_sizes, int n_in,
                              void* d_out, int out_size)
{
    const float* sig = (const float*)d_in[0];
    float* out = (float*)d_out;
    const int B = in_sizes[0] / LSIG;   // 512
    hv_table_kernel<<<NSEEDS, 256>>>(1u);
    hv_combine_kernel<<<B, C_THREADS>>>(sig, out);
}

// round 10
// speedup vs baseline: 1.4074x; 1.0639x over previous
#include <cuda_runtime.h>
#include <stdint.h>

// HypervectorEngine: 512x8192 f32 -> 512x4096 f32 sparse sign output.
// seed = i ^ round(sig*1000) in [0,1024) -> 1024 distinct hypervectors.
// K1: bit-packed sign table; threefry with IMAD adds + 4 widemul rotations (pipe balance).
// K2: combine, uint2 loads x 4-quarter sample split, CSA 5-groups, 4-way merge,
//     byte-packed decode, shfl-scan select (verbatim from R7, bit-exact verified).
// RNG: JAX partitionable threefry, word_j = o0 ^ o1 of threefry(key,(0,j)). (verified R2)

#define NSAMP   100
#define QSAMP   25
#define DIMV    4096
#define KSEL    2048
#define LSIG    8192
#define NSEEDS  1024
#define WPR     (DIMV / 32)        // 128 packed words per hypervector
#define WP2     (WPR / 2)          // 64 word-pairs

__device__ uint32_t g_hv[NSEEDS * WPR];

__device__ __forceinline__ uint32_t addi(uint32_t a, uint32_t b, uint32_t one) {
    uint32_t d;
    asm("mad.lo.u32 %0, %1, %2, %3;" : "=r"(d) : "r"(a), "r"(one), "r"(b));
    return d;
}
__device__ __forceinline__ uint32_t xor3(uint32_t a, uint32_t b, uint32_t c) {
    return a ^ b ^ c;                       // 1 LOP3
}
__device__ __forceinline__ uint32_t maj3(uint32_t a, uint32_t b, uint32_t c) {
    return (a & b) | (c & (a | b));         // 1 LOP3
}
// rotl via widemul: x*2^r (fma) then hi+lo via IMAD (fma). pw = one<<r (opaque).
__device__ __forceinline__ uint32_t rotw(uint32_t x, uint32_t pw, uint32_t one) {
    uint64_t pr;
    asm("mul.wide.u32 %0, %1, %2;" : "=l"(pr) : "r"(x), "r"(pw));
    return addi((uint32_t)(pr >> 32), (uint32_t)pr, one);
}

// JAX threefry2x32, key (0,42), counter (0,c1) -> derived key (fold_in). Cold path.
__device__ __forceinline__ void threefry_key(uint32_t c1, uint32_t& o0, uint32_t& o1)
{
    const uint32_t k0 = 0u, k1 = 42u, k2 = 0u ^ 42u ^ 0x1BD11BDAu;
    uint32_t x0 = k0, x1 = c1 + k1;
    #define R(r) { x0 += x1; x1 = __funnelshift_l(x1, x1, r); x1 ^= x0; }
    R(13) R(15) R(26) R(6)  x0 += k1; x1 += k2 + 1u;
    R(17) R(29) R(16) R(24) x0 += k2; x1 += k0 + 2u;
    R(13) R(15) R(26) R(6)  x0 += k0; x1 += k1 + 3u;
    R(17) R(29) R(16) R(24) x0 += k1; x1 += k2 + 4u;
    R(13) R(15) R(26) R(6)
    o0 = x0 + k2; o1 = x1 + k0 + 5u;
    #undef R
}

// ---------------- Kernel 1: build hypervector sign table ----------------
__global__ void __launch_bounds__(256)
hv_table_kernel(uint32_t one)
{
    const int seed = blockIdx.x;
    const int t    = threadIdx.x;
    const int lane = t & 31;
    const int wrp  = t >> 5;

    __shared__ uint32_t sk0, sk1;
    if (t == 0) {
        uint32_t o0, o1;
        threefry_key((uint32_t)seed, o0, o1);
        sk0 = o0; sk1 = o1;
    }
    __syncthreads();
    const uint32_t k0 = sk0, k1 = sk1, k2 = k0 ^ k1 ^ 0x1BD11BDAu;
    const uint32_t k2p1 = k2 + 1u, k0p2 = k0 + 2u, k1p3 = k1 + 3u;
    const uint32_t k2p4 = k2 + 4u, k0p5 = k0 + 5u;
    const uint32_t k1t  = k1 + (uint32_t)t;
    const uint32_t pw29 = one << 29, pw24 = one << 24;

    uint32_t* dst = g_hv + (size_t)seed * WPR;
#pragma unroll
    for (int p = 0; p < DIMV / 256; p++) {
        uint32_t x0 = k0;
        uint32_t x1 = addi(k1t, (uint32_t)(p * 256), one);
        #define RB(r)  { x0 = addi(x0, x1, one); x1 = __funnelshift_l(x1, x1, r); x1 ^= x0; }
        #define RBW(pw){ x0 = addi(x0, x1, one); x1 = rotw(x1, pw, one); x1 ^= x0; }
        RB(13) RB(15) RB(26) RB(6)
        x0 = addi(x0, k1, one); x1 = addi(x1, k2p1, one);
        RB(17) RBW(pw29) RB(16) RBW(pw24)
        x0 = addi(x0, k2, one); x1 = addi(x1, k0p2, one);
        RB(13) RB(15) RB(26) RB(6)
        x0 = addi(x0, k0, one); x1 = addi(x1, k1p3, one);
        RB(17) RBW(pw29) RB(16) RBW(pw24)
        x0 = addi(x0, k1, one); x1 = addi(x1, k2p4, one);
        RB(13) RB(15) RB(26) RB(6)
        #undef RB
        #undef RBW
        const uint32_t o0 = addi(x0, k2, one);
        const uint32_t o1 = addi(x1, k0p5, one);
        const uint32_t word = __ballot_sync(0xFFFFFFFFu, (int)((o0 ^ o1) >> 31));
        if (lane == 0) dst[p * 8 + wrp] = word;
    }
}

// ---------------- Kernel 2: combine + top-k select (fused) ----------------
#define C_THREADS 256
#define C_BPT     16               // output elems per thread in select phase

__global__ void __launch_bounds__(C_THREADS)
hv_combine_kernel(const float* __restrict__ sig, float* __restrict__ out)
{
    const int b = blockIdx.x;
    const int t = threadIdx.x;
    const int lane = t & 31;
    const int wid  = t >> 5;

    __shared__ int      sseed[NSAMP];
    __shared__ uint32_t spl[4][5][WPR];     // [quarter][plane][word], 10 KB
    __shared__ uint32_t squad[WPR * 8];     // packed n-bytes, 4 KB
    __shared__ int      shist[51];
    __shared__ int      swsum[C_THREADS / 32];
    __shared__ int      sTb, sQuota;

    if (t < NSAMP) {
        const int i   = t;
        const int idx = (i * (LSIG - 1)) / (NSAMP - 1);   // trunc of f32 linspace
        const float s = sig[(size_t)b * LSIG + idx];
        const int val = __float2int_rn(s * 1000.0f);      // jnp.round RNE
        sseed[i] = i ^ val;                                // in [0,1024)
    }
    if (t < 51) shist[t] = 0;
    __syncthreads();

    // ---- accumulate: thread t -> word-pair wp, quarter qt (25 samples, 5 planes/word) ----
    {
        const int wp = t & (WP2 - 1);
        const int qt = t >> 6;                 // 0..3
        const int ibase = qt * QSAMP;
        const uint2* tbl2 = reinterpret_cast<const uint2*>(g_hv);

        uint32_t pa0=0,pa1=0,pa2=0,pa3=0,pa4=0;
        uint32_t pb0=0,pb1=0,pb2=0,pb3=0,pb4=0;
#pragma unroll
        for (int g = 0; g < QSAMP / 5; g++) {
            const int i0 = ibase + g * 5;
            uint2 v0 = tbl2[(size_t)sseed[i0    ] * WP2 + wp];
            uint2 v1 = tbl2[(size_t)sseed[i0 + 1] * WP2 + wp];
            uint2 v2 = tbl2[(size_t)sseed[i0 + 2] * WP2 + wp];
            uint2 v3 = tbl2[(size_t)sseed[i0 + 3] * WP2 + wp];
            uint2 v4 = tbl2[(size_t)sseed[i0 + 4] * WP2 + wp];
            // word A
            {
                uint32_t s1 = xor3(v0.x, v1.x, v2.x);
                uint32_t c1 = maj3(v0.x, v1.x, v2.x);
                uint32_t g1 = xor3(s1, v3.x, v4.x);
                uint32_t c2 = maj3(s1, v3.x, v4.x);
                uint32_t g2 = c1 ^ c2;
                uint32_t g4 = c1 & c2;
                uint32_t cy = pa0 & g1;  pa0 ^= g1;
                uint32_t n1 = xor3(pa1, g2, cy); cy = maj3(pa1, g2, cy); pa1 = n1;
                uint32_t n2 = xor3(pa2, g4, cy); cy = maj3(pa2, g4, cy); pa2 = n2;
                uint32_t n3 = pa3 ^ cy;  cy &= pa3;  pa3 = n3;
                pa4 ^= cy;
            }
            // word B
            {
                uint32_t s1 = xor3(v0.y, v1.y, v2.y);
                uint32_t c1 = maj3(v0.y, v1.y, v2.y);
                uint32_t g1 = xor3(s1, v3.y, v4.y);
                uint32_t c2 = maj3(s1, v3.y, v4.y);
                uint32_t g2 = c1 ^ c2;
                uint32_t g4 = c1 & c2;
                uint32_t cy = pb0 & g1;  pb0 ^= g1;
                uint32_t n1 = xor3(pb1, g2, cy); cy = maj3(pb1, g2, cy); pb1 = n1;
                uint32_t n2 = xor3(pb2, g4, cy); cy = maj3(pb2, g4, cy); pb2 = n2;
                uint32_t n3 = pb3 ^ cy;  cy &= pb3;  pb3 = n3;
                pb4 ^= cy;
            }
        }
        uint2* s2;
        s2 = reinterpret_cast<uint2*>(spl[qt][0]); s2[wp] = make_uint2(pa0, pb0);
        s2 = reinterpret_cast<uint2*>(spl[qt][1]); s2[wp] = make_uint2(pa1, pb1);
        s2 = reinterpret_cast<uint2*>(spl[qt][2]); s2[wp] = make_uint2(pa2, pb2);
        s2 = reinterpret_cast<uint2*>(spl[qt][3]); s2[wp] = make_uint2(pa3, pb3);
        s2 = reinterpret_cast<uint2*>(spl[qt][4]); s2[wp] = make_uint2(pa4, pb4);
    }
    __syncthreads();

    // ---- merge 4 quarters for word w = t>>1; decode quads l = (t&1)*4 .. +3 ----
    const int w  = t >> 1;
    const int hb = t & 1;
    {
        uint32_t a0 = spl[0][0][w], a1 = spl[0][1][w], a2 = spl[0][2][w],
                 a3 = spl[0][3][w], a4 = spl[0][4][w];
        uint32_t b0 = spl[1][0][w], b1 = spl[1][1][w], b2 = spl[1][2][w],
                 b3 = spl[1][3][w], b4 = spl[1][4][w];
        uint32_t c0 = spl[2][0][w], c1 = spl[2][1][w], c2 = spl[2][2][w],
                 c3 = spl[2][3][w], c4 = spl[2][4][w];
        uint32_t d0 = spl[3][0][w], d1 = spl[3][1][w], d2 = spl[3][2][w],
                 d3 = spl[3][3][w], d4 = spl[3][4][w];

        uint32_t m0,m1,m2,m3,m4,m5, n0,n1,n2,n3,n4,n5, cy;
        m0 = a0 ^ b0;        cy = a0 & b0;
        m1 = xor3(a1,b1,cy); cy = maj3(a1,b1,cy);
        m2 = xor3(a2,b2,cy); cy = maj3(a2,b2,cy);
        m3 = xor3(a3,b3,cy); cy = maj3(a3,b3,cy);
        m4 = xor3(a4,b4,cy); cy = maj3(a4,b4,cy);
        m5 = cy;
        n0 = c0 ^ d0;        cy = c0 & d0;
        n1 = xor3(c1,d1,cy); cy = maj3(c1,d1,cy);
        n2 = xor3(c2,d2,cy); cy = maj3(c2,d2,cy);
        n3 = xor3(c3,d3,cy); cy = maj3(c3,d3,cy);
        n4 = xor3(c4,d4,cy); cy = maj3(c4,d4,cy);
        n5 = cy;

        uint32_t r0,r1,r2,r3,r4,r5,r6;
        r0 = m0 ^ n0;        cy = m0 & n0;
        r1 = xor3(m1,n1,cy); cy = maj3(m1,n1,cy);
        r2 = xor3(m2,n2,cy); cy = maj3(m2,n2,cy);
        r3 = xor3(m3,n3,cy); cy = maj3(m3,n3,cy);
        r4 = xor3(m4,n4,cy); cy = maj3(m4,n4,cy);
        r5 = xor3(m5,n5,cy); cy = maj3(m5,n5,cy);
        r6 = cy;

        const int lb = hb * 4;
#pragma unroll
        for (int q = 0; q < 4; q++) {
            const int l = lb + q;
            uint32_t acc;
            acc  =  (r0 >> l) & 0x01010101u;
            acc += ((r1 >> l) & 0x01010101u) << 1;
            acc += ((r2 >> l) & 0x01010101u) << 2;
            acc += ((r3 >> l) & 0x01010101u) << 3;
            acc += ((r4 >> l) & 0x01010101u) << 4;
            acc += ((r5 >> l) & 0x01010101u) << 5;
            acc += ((r6 >> l) & 0x01010101u) << 6;
            squad[w * 8 + l] = acc;        // byte k = n for element w*32 + l + 8k
        }
    }
    __syncthreads();

    // ---- select phase (verbatim R7): thread t owns j = t*16 .. t*16+15 ----
    const int w2 = t >> 1;

    int nv[C_BPT];
#pragma unroll
    for (int q = 0; q < C_BPT; q++) {
        const uint32_t word = squad[w2 * 8 + (q & 7)];
        nv[q] = (int)((word >> (8 * (2 * hb + (q >> 3)))) & 0xFFu);
    }

#pragma unroll
    for (int q = 0; q < C_BPT; q++) {
        int d = nv[q] - 50;
        int bin = d < 0 ? -d : d;
        atomicAdd(&shist[bin], 1);
    }
    __syncthreads();

    if (t < 32) {
        int h1 = shist[50 - t];
        int c1 = h1;
#pragma unroll
        for (int off = 1; off < 32; off <<= 1) {
            int y = __shfl_up_sync(0xFFFFFFFFu, c1, off);
            if (t >= off) c1 += y;
        }
        int total_hi = __shfl_sync(0xFFFFFFFFu, c1, 31);
        if (c1 >= KSEL && c1 - h1 < KSEL) { sTb = 50 - t; sQuota = KSEL - (c1 - h1); }
        int h2 = (t < 19) ? shist[18 - t] : 0;
        int c2 = h2;
#pragma unroll
        for (int off = 1; off < 32; off <<= 1) {
            int y = __shfl_up_sync(0xFFFFFFFFu, c2, off);
            if (t >= off) c2 += y;
        }
        int cum2 = total_hi + c2;
        if (t < 19 && cum2 >= KSEL && cum2 - h2 < KSEL) { sTb = 18 - t; sQuota = KSEL - (cum2 - h2); }
    }
    __syncthreads();
    const int Tb = sTb, quota = sQuota;

    int eq = 0;
#pragma unroll
    for (int q = 0; q < C_BPT; q++) {
        int d = nv[q] - 50;
        int bin = d < 0 ? -d : d;
        eq += (bin == Tb);
    }
    int inc = eq;
#pragma unroll
    for (int off = 1; off < 32; off <<= 1) {
        int y = __shfl_up_sync(0xFFFFFFFFu, inc, off);
        if (lane >= off) inc += y;
    }
    if (lane == 31) swsum[wid] = inc;
    __syncthreads();
    if (t < C_THREADS / 32) {
        int v = swsum[t];
        int s = v;
#pragma unroll
        for (int off = 1; off < C_THREADS / 32; off <<= 1) {
            int y = __shfl_up_sync(0xFFu, s, off);
            if (t >= off) s += y;
        }
        swsum[t] = s - v;
    }
    __syncthreads();
    int rank = swsum[wid] + (inc - eq);

    float4* orow = reinterpret_cast<float4*>(out + (size_t)b * DIMV + t * C_BPT);
#pragma unroll
    for (int v4 = 0; v4 < C_BPT / 4; v4++) {
        float vv[4];
#pragma unroll
        for (int e = 0; e < 4; e++) {
            const int d = 50 - nv[v4 * 4 + e];
            const int a = d < 0 ? -d : d;
            float v = 0.0f;
            if (a > Tb) {
                v = (d > 0) ? 1.0f : -1.0f;
            } else if (a == Tb) {
                if (rank < quota) v = (d > 0) ? 1.0f : ((d < 0) ? -1.0f : 0.0f);
                rank++;
            }
            vv[e] = v;
        }
        orow[v4] = make_float4(vv[0], vv[1], vv[2], vv[3]);
    }
}

extern "C" void kernel_launch(void* const* d_in, const int* in_sizes, int n_in,
                              void* d_out, int out_size)
{
    const float* sig = (const float*)d_in[0];
    float* out = (float*)d_out;
    const int B = in_sizes[0] / LSIG;   // 512
    hv_table_kernel<<<NSEEDS, 256>>>(1u);
    hv_combine_kernel<<<B, C_THREADS>>>(sig, out);
}